// round 1
// baseline (speedup 1.0000x reference)
#include <cuda_runtime.h>

#define NN 50000
#define NE 600000
#define DD 128
#define NL 4
#define MT 64   // GEMM rows per block

// ---------------- scratch (device globals: no allocation allowed) ----------------
__device__ int   g_out_cnt[NN];
__device__ int   g_in_cnt[NN];
__device__ int   g_row_off[NN + 1];
__device__ int   g_cursor[NN];
__device__ int   g_csr_src[NE];
__device__ float g_src_norm[NN];
__device__ float g_dst_norm[NN];
__device__ float g_h0[NN * DD];
__device__ float g_h1[NN * DD];
__device__ float g_agg[NN * DD];

// ---------------- f32x2 helpers (Blackwell packed fp32) ----------------
__device__ __forceinline__ void fma2(unsigned long long& d, unsigned long long a,
                                     unsigned long long b) {
    asm("fma.rn.f32x2 %0, %1, %2, %0;" : "+l"(d) : "l"(a), "l"(b));
}
__device__ __forceinline__ unsigned long long pack2(float x, float y) {
    unsigned long long r;
    asm("mov.b64 %0, {%1, %2};" : "=l"(r) : "f"(x), "f"(y));
    return r;
}

// ---------------- CSR build ----------------
__global__ void k_init() {
    int i = blockIdx.x * blockDim.x + threadIdx.x;
    if (i < NN) { g_out_cnt[i] = 0; g_in_cnt[i] = 0; }
}

__global__ void k_count(const int* __restrict__ src, const int* __restrict__ dst) {
    int e = blockIdx.x * blockDim.x + threadIdx.x;
    if (e < NE) {
        atomicAdd(&g_out_cnt[src[e]], 1);
        atomicAdd(&g_in_cnt[dst[e]], 1);
    }
}

// single-block exclusive scan of g_in_cnt -> g_row_off
__global__ void k_scan() {
    const int T = 1024;
    const int C = (NN + T - 1) / T;  // 49
    __shared__ int part[T];
    int t = threadIdx.x;
    int beg = t * C;
    int end = min(beg + C, NN);
    int s = 0;
    for (int i = beg; i < end; i++) s += g_in_cnt[i];
    part[t] = s;
    __syncthreads();
    for (int off = 1; off < T; off <<= 1) {
        int v = (t >= off) ? part[t - off] : 0;
        __syncthreads();
        part[t] += v;
        __syncthreads();
    }
    int run = (t == 0) ? 0 : part[t - 1];
    for (int i = beg; i < end; i++) {
        g_row_off[i] = run;
        run += g_in_cnt[i];
    }
    if (t == T - 1) g_row_off[NN] = part[T - 1];
}

__global__ void k_norm() {
    int i = blockIdx.x * blockDim.x + threadIdx.x;
    if (i < NN) {
        g_cursor[i]   = g_row_off[i];
        g_src_norm[i] = rsqrtf((float)max(g_out_cnt[i], 1));
        g_dst_norm[i] = rsqrtf((float)max(g_in_cnt[i], 1));
    }
}

__global__ void k_fill(const int* __restrict__ src, const int* __restrict__ dst) {
    int e = blockIdx.x * blockDim.x + threadIdx.x;
    if (e < NE) {
        int d = dst[e];
        int p = atomicAdd(&g_cursor[d], 1);
        g_csr_src[p] = src[e];
    }
}

// ---------------- fused scale + aggregate: agg[n] = dst_norm[n] * sum_{e:dst=n} h[src_e]*src_norm[src_e]
__device__ __forceinline__ const float* pick_in(const float* ext, int sel) {
    return sel == 0 ? ext : (sel == 1 ? g_h0 : g_h1);
}

__global__ void k_agg(const float* __restrict__ ext, int sel) {
    int gw   = (blockIdx.x * blockDim.x + threadIdx.x) >> 5;
    int lane = threadIdx.x & 31;
    if (gw >= NN) return;
    const float4* h4 = (const float4*)pick_in(ext, sel);
    int beg = g_row_off[gw];
    int end = g_row_off[gw + 1];
    float4 acc = make_float4(0.f, 0.f, 0.f, 0.f);
    int j = beg;
    for (; j + 2 <= end; j += 2) {
        int s0 = g_csr_src[j];
        int s1 = g_csr_src[j + 1];
        float n0 = g_src_norm[s0];
        float n1 = g_src_norm[s1];
        float4 v0 = h4[s0 * 32 + lane];
        float4 v1 = h4[s1 * 32 + lane];
        acc.x = fmaf(v0.x, n0, acc.x); acc.y = fmaf(v0.y, n0, acc.y);
        acc.z = fmaf(v0.z, n0, acc.z); acc.w = fmaf(v0.w, n0, acc.w);
        acc.x = fmaf(v1.x, n1, acc.x); acc.y = fmaf(v1.y, n1, acc.y);
        acc.z = fmaf(v1.z, n1, acc.z); acc.w = fmaf(v1.w, n1, acc.w);
    }
    if (j < end) {
        int s0 = g_csr_src[j];
        float n0 = g_src_norm[s0];
        float4 v0 = h4[s0 * 32 + lane];
        acc.x = fmaf(v0.x, n0, acc.x); acc.y = fmaf(v0.y, n0, acc.y);
        acc.z = fmaf(v0.z, n0, acc.z); acc.w = fmaf(v0.w, n0, acc.w);
    }
    float dn = g_dst_norm[gw];
    acc.x *= dn; acc.y *= dn; acc.z *= dn; acc.w *= dn;
    ((float4*)g_agg)[gw * 32 + lane] = acc;
}

// ---------------- GEMM: out = g_agg @ W + b  (f32x2 packed FMA) ----------------
// block: 128 threads, tile MT=64 rows x 128 cols; per thread 8 rows x 8 cols.
// dynamic smem: a_s[MT][132] (padded) + w_s[128][128]
#define GEMM_SMEM ((MT * 132 + DD * DD) * (int)sizeof(float))

__global__ __launch_bounds__(128) void k_gemm(const float* __restrict__ Wl,
                                              const float* __restrict__ bias,
                                              float* __restrict__ ext_out, int out_sel) {
    extern __shared__ float smem[];
    float* a_s = smem;             // 64 x 132
    float* w_s = smem + MT * 132;  // 128 x 128

    int tid = threadIdx.x;
    int tx = tid & 15;   // 16 column groups
    int ty = tid >> 4;   // 8 row groups
    int row0 = blockIdx.x * MT;

    float* out = out_sel == 0 ? ext_out : (out_sel == 1 ? g_h0 : g_h1);

    // load W (128x128 = 4096 float4)
    const float4* W4 = (const float4*)Wl;
    float4* w_s4 = (float4*)w_s;
#pragma unroll
    for (int i = 0; i < 32; i++) w_s4[tid + i * 128] = W4[tid + i * 128];

    // load A tile (64 rows x 32 float4), zero-pad OOB rows
    const float4* A4 = (const float4*)g_agg;
#pragma unroll
    for (int i = 0; i < 16; i++) {
        int li = tid + i * 128;        // 0..2047
        int r = li >> 5, c4 = li & 31;
        int row = row0 + r;
        float4 v = make_float4(0.f, 0.f, 0.f, 0.f);
        if (row < NN) v = A4[row * 32 + c4];
        *(float4*)&a_s[r * 132 + c4 * 4] = v;
    }
    __syncthreads();

    unsigned long long acc[8][4];
#pragma unroll
    for (int r = 0; r < 8; r++)
#pragma unroll
        for (int p = 0; p < 4; p++) acc[r][p] = 0ull;

    // cols for this thread: tx*2 + p*32  (p=0..3), pairs (even) -> conflict-free LDS.64
    // rows for this thread: ty + r*8     (r=0..7) -> warp's two ty differ by 132 floats (bank-safe)
#pragma unroll 4
    for (int k = 0; k < DD; k++) {
        unsigned long long w2[4];
#pragma unroll
        for (int p = 0; p < 4; p++)
            w2[p] = *(const unsigned long long*)&w_s[k * DD + tx * 2 + p * 32];
#pragma unroll
        for (int r = 0; r < 8; r++) {
            float a = a_s[(ty + r * 8) * 132 + k];
            unsigned long long aa = pack2(a, a);
#pragma unroll
            for (int p = 0; p < 4; p++) fma2(acc[r][p], aa, w2[p]);
        }
    }

    // epilogue: + bias, store as 8B
#pragma unroll
    for (int p = 0; p < 4; p++) {
        int col = tx * 2 + p * 32;
        float2 bb = *(const float2*)&bias[col];
        unsigned long long bp = pack2(bb.x, bb.y);
#pragma unroll
        for (int r = 0; r < 8; r++) {
            int row = row0 + ty + r * 8;
            if (row < NN) {
                unsigned long long v;
                asm("add.rn.f32x2 %0, %1, %2;" : "=l"(v) : "l"(acc[r][p]), "l"(bp));
                *(unsigned long long*)&out[row * DD + col] = v;
            }
        }
    }
}

// ---------------- launch ----------------
extern "C" void kernel_launch(void* const* d_in, const int* in_sizes, int n_in,
                              void* d_out, int out_size) {
    const float* feat = (const float*)d_in[0];
    const int*   src  = (const int*)d_in[1];
    const int*   dst  = (const int*)d_in[2];
    const float* W    = (const float*)d_in[3];
    const float* b    = (const float*)d_in[4];
    float* out = (float*)d_out;

    cudaFuncSetAttribute(k_gemm, cudaFuncAttributeMaxDynamicSharedMemorySize, GEMM_SMEM);

    const int TB = 256;
    // CSR build (once per launch, reused by all 4 layers)
    k_init<<<(NN + TB - 1) / TB, TB>>>();
    k_count<<<(NE + TB - 1) / TB, TB>>>(src, dst);
    k_scan<<<1, 1024>>>();
    k_norm<<<(NN + TB - 1) / TB, TB>>>();
    k_fill<<<(NE + TB - 1) / TB, TB>>>(src, dst);

    const int AGG_GRID  = (NN + (TB / 32) - 1) / (TB / 32);  // warp per node
    const int GEMM_GRID = (NN + MT - 1) / MT;

    // layer 0: feat -> g_h0
    k_agg<<<AGG_GRID, TB>>>(feat, 0);
    k_gemm<<<GEMM_GRID, 128, GEMM_SMEM>>>(W + 0 * DD * DD, b + 0 * DD, nullptr, 1);
    // layer 1: g_h0 -> g_h1
    k_agg<<<AGG_GRID, TB>>>(nullptr, 1);
    k_gemm<<<GEMM_GRID, 128, GEMM_SMEM>>>(W + 1 * DD * DD, b + 1 * DD, nullptr, 2);
    // layer 2: g_h1 -> g_h0
    k_agg<<<AGG_GRID, TB>>>(nullptr, 2);
    k_gemm<<<GEMM_GRID, 128, GEMM_SMEM>>>(W + 2 * DD * DD, b + 2 * DD, nullptr, 1);
    // layer 3: g_h0 -> d_out
    k_agg<<<AGG_GRID, TB>>>(nullptr, 1);
    k_gemm<<<GEMM_GRID, 128, GEMM_SMEM>>>(W + 3 * DD * DD, b + 3 * DD, out, 0);
}

// round 4
// speedup vs baseline: 1.2408x; 1.2408x over previous
#include <cuda_runtime.h>
#include <cuda_bf16.h>

#define NN 50000
#define NE 600000
#define DD 128
#define NT 391            // 128-row tiles covering 50048 rows
#define LDA 136           // padded smem row (bf16 units): 272B, conflict-free ldmatrix

// ---------------- scratch (device globals; no allocation allowed) ----------------
__device__ int   g_out_cnt[NN];
__device__ int   g_in_cnt[NN];
__device__ int   g_row_off[NN + 1];
__device__ int   g_cursor[NN];
__device__ int   g_csr_src[NE];
__device__ float g_src_norm[NN];
__device__ float g_dst_norm[NN];
__device__ float g_h0[NN * DD];
__device__ float g_h1[NN * DD];
// bf16 split of aggregated features, row-major [NT*128][128]
__device__ __align__(16) unsigned short g_ah16[NT * DD * DD];
__device__ __align__(16) unsigned short g_al16[NT * DD * DD];
// bf16 split of W (k x n row-major), per layer
__device__ __align__(16) unsigned short g_wh16[4 * DD * DD];
__device__ __align__(16) unsigned short g_wl16[4 * DD * DD];

// ---------------- PTX helpers (base sm_100 compatible only!) ----------------
__device__ __forceinline__ unsigned s2u(const void* p) {
    unsigned r;
    asm("{ .reg .u64 t; cvta.to.shared.u64 t, %1; cvt.u32.u64 %0, t; }" : "=r"(r) : "l"(p));
    return r;
}
#define LDSM_X4(r, a)                                                         \
    asm volatile("ldmatrix.sync.aligned.m8n8.x4.shared.b16 {%0,%1,%2,%3}, [%4];" \
        : "=r"((r)[0]), "=r"((r)[1]), "=r"((r)[2]), "=r"((r)[3]) : "r"(a))
#define LDSM_X4T(r, a)                                                        \
    asm volatile("ldmatrix.sync.aligned.m8n8.x4.trans.shared.b16 {%0,%1,%2,%3}, [%4];" \
        : "=r"((r)[0]), "=r"((r)[1]), "=r"((r)[2]), "=r"((r)[3]) : "r"(a))
#define MMA16816(c, a, b0_, b1_)                                              \
    asm volatile("mma.sync.aligned.m16n8k16.row.col.f32.bf16.bf16.f32 "       \
        "{%0,%1,%2,%3},{%4,%5,%6,%7},{%8,%9},{%0,%1,%2,%3};"                  \
        : "+f"((c)[0]), "+f"((c)[1]), "+f"((c)[2]), "+f"((c)[3])              \
        : "r"((a)[0]), "r"((a)[1]), "r"((a)[2]), "r"((a)[3]), "r"(b0_), "r"(b1_))

// ---------------- CSR build ----------------
__global__ void k_init() {
    int i = blockIdx.x * blockDim.x + threadIdx.x;
    if (i < NN) { g_out_cnt[i] = 0; g_in_cnt[i] = 0; }
}
__global__ void k_count(const int* __restrict__ src, const int* __restrict__ dst) {
    int e = blockIdx.x * blockDim.x + threadIdx.x;
    if (e < NE) {
        atomicAdd(&g_out_cnt[src[e]], 1);
        atomicAdd(&g_in_cnt[dst[e]], 1);
    }
}
__global__ void k_scan() {
    const int T = 1024;
    const int C = (NN + T - 1) / T;
    __shared__ int part[T];
    int t = threadIdx.x;
    int beg = t * C, end = min(beg + C, NN);
    int s = 0;
    for (int i = beg; i < end; i++) s += g_in_cnt[i];
    part[t] = s;
    __syncthreads();
    for (int off = 1; off < T; off <<= 1) {
        int v = (t >= off) ? part[t - off] : 0;
        __syncthreads();
        part[t] += v;
        __syncthreads();
    }
    int run = (t == 0) ? 0 : part[t - 1];
    for (int i = beg; i < end; i++) { g_row_off[i] = run; run += g_in_cnt[i]; }
    if (t == T - 1) g_row_off[NN] = part[T - 1];
}
__global__ void k_norm() {
    int i = blockIdx.x * blockDim.x + threadIdx.x;
    if (i < NN) {
        g_cursor[i]   = g_row_off[i];
        g_src_norm[i] = rsqrtf((float)max(g_out_cnt[i], 1));
        g_dst_norm[i] = rsqrtf((float)max(g_in_cnt[i], 1));
    }
}
__global__ void k_fill(const int* __restrict__ src, const int* __restrict__ dst) {
    int e = blockIdx.x * blockDim.x + threadIdx.x;
    if (e < NE) {
        int d = dst[e];
        int p = atomicAdd(&g_cursor[d], 1);
        g_csr_src[p] = src[e];
    }
}

// ---------------- W split (k x n row-major, elementwise) ----------------
__global__ void k_wconv(const float* __restrict__ W) {
    int idx = blockIdx.x * blockDim.x + threadIdx.x;
    if (idx >= 4 * DD * DD) return;
    float v = W[idx];
    __nv_bfloat16 hi = __float2bfloat16(v);
    float lo = v - __bfloat162float(hi);
    g_wh16[idx] = __bfloat16_as_ushort(hi);
    g_wl16[idx] = __bfloat16_as_ushort(__float2bfloat16(lo));
}

// ---------------- fused scale + aggregate -> bf16 hi/lo row-major ----------------
__device__ __forceinline__ const float* pick_in(const float* ext, int sel) {
    return sel == 0 ? ext : (sel == 1 ? g_h0 : g_h1);
}

__global__ void k_agg(const float* __restrict__ ext, int sel) {
    int gw   = (blockIdx.x * blockDim.x + threadIdx.x) >> 5;
    int lane = threadIdx.x & 31;
    if (gw >= NN) return;
    const float4* h4 = (const float4*)pick_in(ext, sel);
    int beg = g_row_off[gw], end = g_row_off[gw + 1];
    float4 acc = make_float4(0.f, 0.f, 0.f, 0.f);
    int j = beg;
    for (; j + 2 <= end; j += 2) {
        int s0 = g_csr_src[j], s1 = g_csr_src[j + 1];
        float n0 = g_src_norm[s0], n1 = g_src_norm[s1];
        float4 v0 = h4[s0 * 32 + lane];
        float4 v1 = h4[s1 * 32 + lane];
        acc.x = fmaf(v0.x, n0, acc.x); acc.y = fmaf(v0.y, n0, acc.y);
        acc.z = fmaf(v0.z, n0, acc.z); acc.w = fmaf(v0.w, n0, acc.w);
        acc.x = fmaf(v1.x, n1, acc.x); acc.y = fmaf(v1.y, n1, acc.y);
        acc.z = fmaf(v1.z, n1, acc.z); acc.w = fmaf(v1.w, n1, acc.w);
    }
    if (j < end) {
        int s0 = g_csr_src[j];
        float n0 = g_src_norm[s0];
        float4 v0 = h4[s0 * 32 + lane];
        acc.x = fmaf(v0.x, n0, acc.x); acc.y = fmaf(v0.y, n0, acc.y);
        acc.z = fmaf(v0.z, n0, acc.z); acc.w = fmaf(v0.w, n0, acc.w);
    }
    float dn = g_dst_norm[gw];
    acc.x *= dn; acc.y *= dn; acc.z *= dn; acc.w *= dn;

    __nv_bfloat16 hx = __float2bfloat16(acc.x), hy = __float2bfloat16(acc.y);
    __nv_bfloat16 hz = __float2bfloat16(acc.z), hw = __float2bfloat16(acc.w);
    ushort4 vh, vl;
    vh.x = __bfloat16_as_ushort(hx); vh.y = __bfloat16_as_ushort(hy);
    vh.z = __bfloat16_as_ushort(hz); vh.w = __bfloat16_as_ushort(hw);
    vl.x = __bfloat16_as_ushort(__float2bfloat16(acc.x - __bfloat162float(hx)));
    vl.y = __bfloat16_as_ushort(__float2bfloat16(acc.y - __bfloat162float(hy)));
    vl.z = __bfloat16_as_ushort(__float2bfloat16(acc.z - __bfloat162float(hz)));
    vl.w = __bfloat16_as_ushort(__float2bfloat16(acc.w - __bfloat162float(hw)));
    size_t o = (size_t)gw * DD + lane * 4;
    *(ushort4*)&g_ah16[o] = vh;
    *(ushort4*)&g_al16[o] = vl;
}

// ---------------- tensor-core GEMM via mma.sync (bf16 3-term split) ----------------
// CTA: 256 thr (8 warps), tile 128 rows x 128 cols. smem: Ah|Al|Wh|Wl, 128x136 bf16 each.
#define GSMEM (4 * DD * LDA * 2)

__global__ __launch_bounds__(256) void k_mgemm(int layer, const float* __restrict__ bias,
                                               float* __restrict__ ext_out, int out_sel) {
    extern __shared__ unsigned short sm[];
    unsigned short* sAh = sm;
    unsigned short* sAl = sm + DD * LDA;
    unsigned short* sWh = sm + 2 * DD * LDA;
    unsigned short* sWl = sm + 3 * DD * LDA;

    int tid = threadIdx.x, lane = tid & 31, w = tid >> 5;
    int t = blockIdx.x;
    float* out = out_sel == 0 ? ext_out : (out_sel == 1 ? g_h0 : g_h1);

    // stage tiles (16B vectors); pad cols 128..135 never read
    {
        const uint4* a_h = (const uint4*)(g_ah16 + (size_t)t * DD * DD);
        const uint4* a_l = (const uint4*)(g_al16 + (size_t)t * DD * DD);
        const uint4* w_h = (const uint4*)(g_wh16 + layer * DD * DD);
        const uint4* w_l = (const uint4*)(g_wl16 + layer * DD * DD);
#pragma unroll
        for (int i = 0; i < 8; i++) {
            int li = tid + i * 256;          // 0..2047
            int r = li >> 4, c = li & 15;
            int d = r * LDA + c * 8;
            *(uint4*)&sAh[d] = a_h[li];
            *(uint4*)&sAl[d] = a_l[li];
            *(uint4*)&sWh[d] = w_h[li];
            *(uint4*)&sWl[d] = w_l[li];
        }
    }
    __syncthreads();

    float acc[16][4];
#pragma unroll
    for (int nt = 0; nt < 16; nt++)
#pragma unroll
        for (int q = 0; q < 4; q++) acc[nt][q] = 0.f;

    int m0 = w * 16;
    // A x4: mats = rows[0:8],rows[8:16] x kcols{0,8}; addr = row (m0 + lane%16), col (lane/16)*8
    unsigned aH = s2u(&sAh[(m0 + (lane & 15)) * LDA + (lane >> 4) * 8]);
    unsigned aL = s2u(&sAl[(m0 + (lane & 15)) * LDA + (lane >> 4) * 8]);
    // fused B x4.trans: threads 0-15 -> Wh rows, 16-31 -> Wl rows (same k-rows)
    unsigned bB = (lane < 16) ? s2u(&sWh[(lane & 15) * LDA]) : s2u(&sWl[(lane & 15) * LDA]);

#pragma unroll
    for (int ks = 0; ks < 8; ks++) {
        unsigned ah[4], al[4];
        LDSM_X4(ah, aH + ks * 32);                 // +16 bf16 cols per k-step
        LDSM_X4(al, aL + ks * 32);
#pragma unroll
        for (int nt = 0; nt < 16; nt++) {
            unsigned b[4];                         // b[0..1]=Wh frag, b[2..3]=Wl frag
            LDSM_X4T(b, bB + ks * 16 * LDA * 2 + nt * 16);
            MMA16816(acc[nt], ah, b[0], b[1]);     // Ah*Wh
            MMA16816(acc[nt], ah, b[2], b[3]);     // Ah*Wl
            MMA16816(acc[nt], al, b[0], b[1]);     // Al*Wh
        }
    }

    // epilogue: thread holds rows (m0 + lane/4) and +8, cols nt*8 + (lane%4)*2
    int r0 = t * DD + m0 + (lane >> 2);
    int r1 = r0 + 8;
#pragma unroll
    for (int nt = 0; nt < 16; nt++) {
        int col = nt * 8 + (lane & 3) * 2;
        float2 bb = *(const float2*)&bias[col];
        if (r0 < NN) {
            float2 v; v.x = acc[nt][0] + bb.x; v.y = acc[nt][1] + bb.y;
            *(float2*)&out[(size_t)r0 * DD + col] = v;
        }
        if (r1 < NN) {
            float2 v; v.x = acc[nt][2] + bb.x; v.y = acc[nt][3] + bb.y;
            *(float2*)&out[(size_t)r1 * DD + col] = v;
        }
    }
}

// ---------------- launch ----------------
extern "C" void kernel_launch(void* const* d_in, const int* in_sizes, int n_in,
                              void* d_out, int out_size) {
    const float* feat = (const float*)d_in[0];
    const int*   src  = (const int*)d_in[1];
    const int*   dst  = (const int*)d_in[2];
    const float* W    = (const float*)d_in[3];
    const float* b    = (const float*)d_in[4];
    float* out = (float*)d_out;

    cudaFuncSetAttribute(k_mgemm, cudaFuncAttributeMaxDynamicSharedMemorySize, GSMEM);

    const int TB = 256;
    k_init<<<(NN + TB - 1) / TB, TB>>>();
    k_count<<<(NE + TB - 1) / TB, TB>>>(src, dst);
    k_scan<<<1, 1024>>>();
    k_norm<<<(NN + TB - 1) / TB, TB>>>();
    k_fill<<<(NE + TB - 1) / TB, TB>>>(src, dst);
    k_wconv<<<(4 * DD * DD + TB - 1) / TB, TB>>>(W);

    const int AGG_GRID = (NN + (TB / 32) - 1) / (TB / 32);

    k_agg<<<AGG_GRID, TB>>>(feat, 0);
    k_mgemm<<<NT, 256, GSMEM>>>(0, b + 0 * DD, nullptr, 1);
    k_agg<<<AGG_GRID, TB>>>(nullptr, 1);
    k_mgemm<<<NT, 256, GSMEM>>>(1, b + 1 * DD, nullptr, 2);
    k_agg<<<AGG_GRID, TB>>>(nullptr, 2);
    k_mgemm<<<NT, 256, GSMEM>>>(2, b + 2 * DD, nullptr, 1);
    k_agg<<<AGG_GRID, TB>>>(nullptr, 1);
    k_mgemm<<<NT, 256, GSMEM>>>(3, b + 3 * DD, out, 0);
}